// round 13
// baseline (speedup 1.0000x reference)
#include <cuda_runtime.h>
#include <cuda_fp16.h>
#include <cstdint>

#define Hd 1024
#define Fd 2048
#define Td 8192

// ---------------- scratch (__device__ globals; no allocs allowed) -------------
__device__ __align__(16) float g_wts[Td * 4];    // w0, w1, w2, w1+w2
__device__ __align__(16) float g_cvec[2][Fd];    // b_d @ ad_w1 + ad_b1
__device__ __align__(16) __half g_xp[(size_t)Td * Hd];      // packed norm(x)
__device__ __align__(16) __half g_Bp[2 * (size_t)Fd * Hd];  // packed W1^T scaled
__device__ __align__(16) __half g_W2p[(size_t)Hd * Fd];     // packed W2^T
__device__ __align__(16) __half g_gp[(size_t)Td * Fd];      // packed activation

// ---------------- PTX helpers -------------------------------------------------
__device__ __forceinline__ uint32_t smem_u32(const void* p) {
    uint32_t a;
    asm("{ .reg .u64 t; cvta.to.shared.u64 t, %1; cvt.u32.u64 %0, t; }"
        : "=r"(a) : "l"(p));
    return a;
}
#define LDSM4(r, a) \
    asm volatile("ldmatrix.sync.aligned.m8n8.x4.shared.b16 {%0,%1,%2,%3}, [%4];" \
                 : "=r"((r)[0]), "=r"((r)[1]), "=r"((r)[2]), "=r"((r)[3]) : "r"(a))
#define MBAR_INIT(a, c)  asm volatile("mbarrier.init.shared.b64 [%0], %1;" :: "r"(a), "r"((uint32_t)(c)) : "memory")
#define MBAR_EXPECT(a, tx) asm volatile("mbarrier.arrive.expect_tx.shared.b64 _, [%0], %1;" :: "r"(a), "r"((uint32_t)(tx)) : "memory")
#define MBAR_WAIT(a, p) do { \
    uint32_t _m = (a), _p = (uint32_t)(p), _d; \
    asm volatile("{\n\t.reg .pred q;\n\tmbarrier.try_wait.parity.acquire.cta.shared::cta.b64 q, [%1], %2;\n\tselp.b32 %0,1,0,q;\n\t}" \
                 : "=r"(_d) : "r"(_m), "r"(_p) : "memory"); \
    if (!_d) { \
        asm volatile("{\n\t.reg .pred q;\n\tLW_%=:\n\tmbarrier.try_wait.parity.acquire.cta.shared::cta.b64 q, [%0], %1, 0x989680;\n\t@q bra.uni LD_%=;\n\tbra.uni LW_%=;\n\tLD_%=:\n\t}" \
                     :: "r"(_m), "r"(_p) : "memory"); \
    } } while (0)
#define BULK(dst, src, sz, mb) \
    asm volatile("cp.async.bulk.shared::cluster.global.mbarrier::complete_tx::bytes [%0], [%1], %2, [%3];" \
                 :: "r"(dst), "l"(__cvta_generic_to_global(src)), "r"((uint32_t)(sz)), "r"(mb) : "memory")

__device__ __forceinline__ void mma_f16(float* d, const uint32_t* a,
                                        uint32_t b0, uint32_t b1) {
    asm volatile(
        "mma.sync.aligned.m16n8k16.row.col.f32.f16.f16.f32 "
        "{%0,%1,%2,%3}, {%4,%5,%6,%7}, {%8,%9}, {%0,%1,%2,%3};"
        : "+f"(d[0]), "+f"(d[1]), "+f"(d[2]), "+f"(d[3])
        : "r"(a[0]), "r"(a[1]), "r"(a[2]), "r"(a[3]), "r"(b0), "r"(b1));
}

__device__ __forceinline__ uint32_t hpack(float a, float b) {
    const __half2 h = __floats2half2_rn(a, b);
    return *(const uint32_t*)&h;
}
__device__ __forceinline__ size_t gp_off(int m, int f) {   // halves offset in g_gp
    return ((size_t)((m >> 7) * 64 + (f >> 5))) * 4096 +
           ((f >> 3) & 3) * 1024 + (m & 127) * 8 + (f & 7);
}

// ---------------- fused prep: trans1 | trans2 | prepc | gate ------------------
// block ranges: [0,2048) trans1, [2048,4096) trans2, [4096,4224) prepc,
//               [4224,5248) gate. All 256 threads. Vectorized uint4 stores.
__global__ void k_prep(const float* __restrict__ x, const int* __restrict__ dm,
                       const float* __restrict__ gw1, const float* __restrict__ gb1,
                       const float* __restrict__ gw2, const float* __restrict__ gb2,
                       const float* __restrict__ sb, const float* __restrict__ si,
                       const float* __restrict__ bb, const float* __restrict__ bi,
                       const float* __restrict__ aw1, const float* __restrict__ ab1,
                       const float* __restrict__ aw2) {
    __shared__ float sh[32 * 33];
    const int b = blockIdx.x;
    const int tid = threadIdx.x;

    if (b < 2048) {                    // ---- trans1: W1 -> packed, 2 domains
        const int tx = tid & 31, ty = tid >> 5;
        const int f0 = (b & 63) * 32, h0 = (b >> 6) * 32;
        #pragma unroll
        for (int i = 0; i < 4; i++) {
            const int h = h0 + ty + i * 8;
            sh[(ty + i * 8) * 33 + tx] = aw1[(size_t)h * Fd + f0 + tx];
        }
        __syncthreads();
        const int dom = tid >> 7, idx = tid & 127;
        const int hg = idx >> 5, fl = idx & 31;
        const int fo = f0 + fl;
        const float* sv = dom ? si : sb;
        uint32_t pk[4];
        #pragma unroll
        for (int q = 0; q < 4; q++) {
            const int hq = hg * 8 + 2 * q;
            const float v0 = sh[hq * 33 + fl] * __ldg(sv + h0 + hq);
            const float v1 = sh[(hq + 1) * 33 + fl] * __ldg(sv + h0 + hq + 1);
            pk[q] = hpack(v0, v1);
        }
        const int c = h0 >> 5;
        const size_t off = ((size_t)((fo >> 6) * 32 + c)) * 2048 +
                           hg * 512 + (fo & 63) * 8;
        *(uint4*)(g_Bp + (size_t)dom * Fd * Hd + off) = *(uint4*)pk;
    } else if (b < 4096) {             // ---- trans2: W2 -> packed
        const int bb2 = b - 2048;
        const int tx = tid & 31, ty = tid >> 5;
        const int h0 = (bb2 & 31) * 32, f0 = (bb2 >> 5) * 32;
        #pragma unroll
        for (int i = 0; i < 4; i++) {
            const int f = f0 + ty + i * 8;
            sh[(ty + i * 8) * 33 + tx] = aw2[(size_t)f * Hd + h0 + tx];
        }
        __syncthreads();
        if (tid < 128) {
            const int fg = tid >> 5, hl = tid & 31;
            const int ho = h0 + hl;
            uint32_t pk[4];
            #pragma unroll
            for (int q = 0; q < 4; q++) {
                const int fq = fg * 8 + 2 * q;
                pk[q] = hpack(sh[fq * 33 + hl], sh[(fq + 1) * 33 + hl]);
            }
            const int c = f0 >> 5;
            const size_t off = ((size_t)((ho >> 7) * 64 + c)) * 4096 +
                               fg * 1024 + (ho & 127) * 8;
            *(uint4*)(g_W2p + off) = *(uint4*)pk;
        }
    } else if (b < 4224) {             // ---- prepc: c_d = b_d @ W1 + ad_b1
        const int lane32 = tid & 31;
        const int ks = tid >> 5;
        const int i = (b - 4096) * 32 + lane32;
        const int d = i >> 11;
        const int f = i & (Fd - 1);
        const float* bv = d ? bi : bb;
        float acc = 0.f;
        #pragma unroll 8
        for (int h = ks * 128; h < ks * 128 + 128; h++)
            acc = fmaf(__ldg(bv + h), aw1[(size_t)h * Fd + f], acc);
        sh[ks * 32 + lane32] = acc;
        __syncthreads();
        if (ks == 0) {
            float s = sh[lane32];
            #pragma unroll
            for (int q = 1; q < 8; q++) s += sh[q * 32 + lane32];
            g_cvec[d][f] = ab1[f] + s;
        }
    } else {                           // ---- gate: LN stats + weights + xp
        const int t = (b - 4224) * 8 + (tid >> 5);
        const int lane = tid & 31;
        const float* xr = x + (size_t)t * Hd;

        float4 xv[8];
        float s = 0.f, ss = 0.f, a0 = 0.f, a1 = 0.f, a2 = 0.f, a3 = 0.f;
        #pragma unroll
        for (int it = 0; it < 4; it++) {
            const int h = lane * 8 + it * 256;
            xv[2 * it] = *(const float4*)(xr + h);
            xv[2 * it + 1] = *(const float4*)(xr + h + 4);
            const float* vv = (const float*)&xv[2 * it];
            const float4* gw = (const float4*)(gw1 + h * 4);
            #pragma unroll
            for (int q = 0; q < 8; q++) {
                const float v = vv[q];
                s += v; ss += v * v;
                const float4 wr = gw[q];
                a0 += v * wr.x; a1 += v * wr.y; a2 += v * wr.z; a3 += v * wr.w;
            }
        }
        #pragma unroll
        for (int o = 16; o; o >>= 1) {
            s  += __shfl_xor_sync(0xffffffffu, s, o);
            ss += __shfl_xor_sync(0xffffffffu, ss, o);
            a0 += __shfl_xor_sync(0xffffffffu, a0, o);
            a1 += __shfl_xor_sync(0xffffffffu, a1, o);
            a2 += __shfl_xor_sync(0xffffffffu, a2, o);
            a3 += __shfl_xor_sync(0xffffffffu, a3, o);
        }
        const float mean = s * (1.f / Hd);
        const float var = ss * (1.f / Hd) - mean * mean;
        const float rstd = rsqrtf(var + 1e-6f);

        const int mb = t >> 7, r = t & 127;
        #pragma unroll
        for (int it = 0; it < 4; it++) {
            const int h = lane * 8 + it * 256;
            const int c = h >> 5, kb = (h >> 3) & 3;
            const float* vv = (const float*)&xv[2 * it];
            uint4 o;
            o.x = hpack((vv[0] - mean) * rstd, (vv[1] - mean) * rstd);
            o.y = hpack((vv[2] - mean) * rstd, (vv[3] - mean) * rstd);
            o.z = hpack((vv[4] - mean) * rstd, (vv[5] - mean) * rstd);
            o.w = hpack((vv[6] - mean) * rstd, (vv[7] - mean) * rstd);
            *(uint4*)(g_xp + ((size_t)(mb * 32 + c)) * 4096 + kb * 1024 + r * 8) = o;
        }

        if (lane == 0) {
            float hv[4] = {fmaxf(a0 + gb1[0], 0.f), fmaxf(a1 + gb1[1], 0.f),
                           fmaxf(a2 + gb1[2], 0.f), fmaxf(a3 + gb1[3], 0.f)};
            float lg[4];
            #pragma unroll
            for (int e = 0; e < 4; e++) {
                float acc = gb2[e];
                #pragma unroll
                for (int d = 0; d < 4; d++) acc += hv[d] * gw2[d * 4 + e];
                if (dm[e] == 0) acc = -1e9f;
                lg[e] = acc;
            }
            const float mx = fmaxf(fmaxf(lg[0], lg[1]), fmaxf(lg[2], lg[3]));
            const float e0 = expf(lg[0] - mx), e1 = expf(lg[1] - mx);
            const float e2 = expf(lg[2] - mx), e3 = expf(lg[3] - mx);
            const float inv = 1.f / (e0 + e1 + e2 + e3);
            g_wts[4 * t + 0] = e0 * inv;
            g_wts[4 * t + 1] = e1 * inv;
            g_wts[4 * t + 2] = e2 * inv;
            g_wts[4 * t + 3] = (e1 + e2) * inv;
        }
    }
}

// ---------------- kernel: up GEMM (TMA bulk, warp 64x64, 128 thr) -------------
// CTA 128m x 64f x 2dom, 4 warps: dom = wid>>1, mw = (wid&1)*64; warp 64m x 64f.
// Stage (32KB): A 16K | B_book 8K | B_iwslt 8K; 3 stages + mbarriers.
#define UP_SMEM  98368
#define UP_STAGE 32768
__global__ void __launch_bounds__(128, 2) k_up() {
    extern __shared__ char smem[];
    const uint32_t sm = smem_u32(smem);
    const uint32_t mbb = sm + 98304;
    const int tid = threadIdx.x, lane = tid & 31, wid = tid >> 5;
    const int mb = blockIdx.y, nb = blockIdx.x;
    const int m0 = mb * 128, n0 = nb * 64;
    const int dom = wid >> 1, mw = (wid & 1) * 64;
    const int aRow = lane & 15, aK = lane >> 4;
    const int bRow = (lane & 7) + ((lane >> 4) << 3), bK = (lane >> 3) & 1;

    float acc[4][8][4];
    #pragma unroll
    for (int i = 0; i < 4; i++)
        #pragma unroll
        for (int n = 0; n < 8; n++)
            #pragma unroll
            for (int q = 0; q < 4; q++) acc[i][n][q] = 0.f;

    auto issue = [&](int c, int st) {
        const uint32_t mbar = mbb + st * 8;
        const uint32_t dst = sm + st * UP_STAGE;
        MBAR_EXPECT(mbar, 32768);
        BULK(dst, g_xp + ((size_t)(mb * 32 + c * 2)) * 4096, 16384, mbar);
        BULK(dst + 16384, g_Bp + ((size_t)(nb * 32 + c * 2)) * 2048, 8192, mbar);
        BULK(dst + 24576, g_Bp + (size_t)Fd * Hd + ((size_t)(nb * 32 + c * 2)) * 2048, 8192, mbar);
    };

    if (tid == 0) {
        #pragma unroll
        for (int st = 0; st < 3; st++) MBAR_INIT(mbb + st * 8, 1);
    }
    __syncthreads();
    if (tid == 0) { issue(0, 0); issue(1, 1); }

    int st = 0, ph = 0, st2 = 2;
    #pragma unroll 1
    for (int c = 0; c < 16; c++) {
        __syncthreads();                     // stage st2 free for reuse
        if (tid == 0 && c + 2 < 16) issue(c + 2, st2);
        MBAR_WAIT(mbb + st * 8, ph);
        const uint32_t smA = sm + st * UP_STAGE;
        const uint32_t smB = smA + 16384 + dom * 8192;
        #pragma unroll
        for (int j = 0; j < 4; j++) {
            uint32_t a[4][4];
            const uint32_t aBase = smA + (j >> 1) * 8192 +
                (((2 * (j & 1) + aK) << 7) + mw + aRow) * 16;
            #pragma unroll
            for (int i = 0; i < 4; i++) LDSM4(a[i], aBase + i * 256);
            uint32_t b[4][4];
            const uint32_t bBase = smB + (j >> 1) * 4096 +
                (((2 * (j & 1) + bK) << 6) + bRow) * 16;
            #pragma unroll
            for (int nbb = 0; nbb < 4; nbb++) LDSM4(b[nbb], bBase + nbb * 256);
            #pragma unroll
            for (int i = 0; i < 4; i++)
                #pragma unroll
                for (int nbb = 0; nbb < 4; nbb++) {
                    mma_f16(acc[i][2 * nbb + 0], a[i], b[nbb][0], b[nbb][1]);
                    mma_f16(acc[i][2 * nbb + 1], a[i], b[nbb][2], b[nbb][3]);
                }
        }
        if (++st2 == 3) st2 = 0;
        if (++st == 3) { st = 0; ph ^= 1; }
    }

    // --- epilogue: dom1 -> smem (w2*relu), dom0 combines, writes packed g -----
    __syncthreads();
    const int g = lane >> 2, tq = lane & 3;
    float* ex = (float*)smem;               // [128][68] f32 = 34.8KB
    if (dom == 1) {
        #pragma unroll
        for (int i = 0; i < 4; i++) {
            const int r = mw + 16 * i + g;
            const float w2a = g_wts[4 * (m0 + r) + 2];
            const float w2b = g_wts[4 * (m0 + r + 8) + 2];
            #pragma unroll
            for (int n = 0; n < 8; n++) {
                const int col = 8 * n + 2 * tq;
                const float cv0 = g_cvec[1][n0 + col], cv1 = g_cvec[1][n0 + col + 1];
                float2 v0, v1;
                v0.x = w2a * fmaxf(acc[i][n][0] + cv0, 0.f);
                v0.y = w2a * fmaxf(acc[i][n][1] + cv1, 0.f);
                v1.x = w2b * fmaxf(acc[i][n][2] + cv0, 0.f);
                v1.y = w2b * fmaxf(acc[i][n][3] + cv1, 0.f);
                *(float2*)(ex + (size_t)r * 68 + col) = v0;
                *(float2*)(ex + (size_t)(r + 8) * 68 + col) = v1;
            }
        }
    }
    __syncthreads();
    if (dom == 0) {
        #pragma unroll
        for (int i = 0; i < 4; i++) {
            const int r = mw + 16 * i + g;
            const float w1a = g_wts[4 * (m0 + r) + 1];
            const float w1b = g_wts[4 * (m0 + r + 8) + 1];
            #pragma unroll
            for (int n = 0; n < 8; n++) {
                const int col = 8 * n + 2 * tq;
                const int fg = n0 + col;
                const float cv0 = g_cvec[0][fg], cv1 = g_cvec[0][fg + 1];
                const float2 s0 = *(const float2*)(ex + (size_t)r * 68 + col);
                const float2 s1 = *(const float2*)(ex + (size_t)(r + 8) * 68 + col);
                const float g0 = w1a * fmaxf(acc[i][n][0] + cv0, 0.f) + s0.x;
                const float g1 = w1a * fmaxf(acc[i][n][1] + cv1, 0.f) + s0.y;
                const float g2 = w1b * fmaxf(acc[i][n][2] + cv0, 0.f) + s1.x;
                const float g3 = w1b * fmaxf(acc[i][n][3] + cv1, 0.f) + s1.y;
                *(uint32_t*)(g_gp + gp_off(m0 + r, fg)) = hpack(g0, g1);
                *(uint32_t*)(g_gp + gp_off(m0 + r + 8, fg)) = hpack(g2, g3);
            }
        }
    }
}

// ---------------- kernel: down GEMM (TMA bulk, warp 64x64, 128 thr) -----------
// CTA 128m x 128h, 4 warps 2m x 2n, warp 64m x 64h.
// Stage (32KB): A 16K | B 16K; 3 stages + mbarriers.
#define DN_SMEM  98368
#define DN_STAGE 32768
__global__ void __launch_bounds__(128, 2) k_down(const float* __restrict__ x,
                                                 const float* __restrict__ b2,
                                                 float* __restrict__ out) {
    extern __shared__ char smem[];
    const uint32_t sm = smem_u32(smem);
    const uint32_t mbb = sm + 98304;
    const int tid = threadIdx.x, lane = tid & 31, wid = tid >> 5;
    const int mb = blockIdx.y, hb = blockIdx.x;
    const int m0 = mb * 128, n0 = hb * 128;
    const int mw = (wid & 1) * 64, nw = (wid >> 1) * 64;
    const int aRow = lane & 15, aK = lane >> 4;
    const int bRow = (lane & 7) + ((lane >> 4) << 3), bK = (lane >> 3) & 1;

    float acc[4][8][4];
    #pragma unroll
    for (int i = 0; i < 4; i++)
        #pragma unroll
        for (int n = 0; n < 8; n++)
            #pragma unroll
            for (int q = 0; q < 4; q++) acc[i][n][q] = 0.f;

    auto issue = [&](int c, int st) {
        const uint32_t mbar = mbb + st * 8;
        const uint32_t dst = sm + st * DN_STAGE;
        MBAR_EXPECT(mbar, 32768);
        BULK(dst, g_gp + ((size_t)(mb * 64 + c * 2)) * 4096, 16384, mbar);
        BULK(dst + 16384, g_W2p + ((size_t)(hb * 64 + c * 2)) * 4096, 16384, mbar);
    };

    if (tid == 0) {
        #pragma unroll
        for (int st = 0; st < 3; st++) MBAR_INIT(mbb + st * 8, 1);
    }
    __syncthreads();
    if (tid == 0) { issue(0, 0); issue(1, 1); }

    int st = 0, ph = 0, st2 = 2;
    #pragma unroll 1
    for (int c = 0; c < 32; c++) {
        __syncthreads();
        if (tid == 0 && c + 2 < 32) issue(c + 2, st2);
        MBAR_WAIT(mbb + st * 8, ph);
        const uint32_t smA = sm + st * DN_STAGE;
        const uint32_t smB = smA + 16384;
        #pragma unroll
        for (int j = 0; j < 4; j++) {
            uint32_t a[4][4];
            const uint32_t aBase = smA + (j >> 1) * 8192 +
                (((2 * (j & 1) + aK) << 7) + mw + aRow) * 16;
            #pragma unroll
            for (int i = 0; i < 4; i++) LDSM4(a[i], aBase + i * 256);
            uint32_t b[4][4];
            const uint32_t bBase = smB + (j >> 1) * 8192 +
                (((2 * (j & 1) + bK) << 7) + nw + bRow) * 16;
            #pragma unroll
            for (int nbb = 0; nbb < 4; nbb++) LDSM4(b[nbb], bBase + nbb * 256);
            #pragma unroll
            for (int i = 0; i < 4; i++)
                #pragma unroll
                for (int nbb = 0; nbb < 4; nbb++) {
                    mma_f16(acc[i][2 * nbb + 0], a[i], b[nbb][0], b[nbb][1]);
                    mma_f16(acc[i][2 * nbb + 1], a[i], b[nbb][2], b[nbb][3]);
                }
        }
        if (++st2 == 3) st2 = 0;
        if (++st == 3) { st = 0; ph ^= 1; }
    }

    // --- epilogue: out = x*(1+w0) + acc + (w1+w2)*b2 --------------------------
    const int g = lane >> 2, tq = lane & 3;
    #pragma unroll
    for (int i = 0; i < 4; i++) {
        const int r0 = m0 + mw + 16 * i + g;
        const float4 wv0 = *(const float4*)&g_wts[4 * r0];
        const float4 wv1 = *(const float4*)&g_wts[4 * (r0 + 8)];
        const float xs0 = 1.f + wv0.x, w120 = wv0.w;
        const float xs1 = 1.f + wv1.x, w121 = wv1.w;
        #pragma unroll
        for (int n = 0; n < 8; n++) {
            const int h = n0 + nw + 8 * n + 2 * tq;
            const float2 xa = *(const float2*)&x[(size_t)r0 * Hd + h];
            const float2 xb = *(const float2*)&x[(size_t)(r0 + 8) * Hd + h];
            const float2 bv = *(const float2*)&b2[h];
            float2 o0, o1;
            o0.x = xa.x * xs0 + acc[i][n][0] + w120 * bv.x;
            o0.y = xa.y * xs0 + acc[i][n][1] + w120 * bv.y;
            o1.x = xb.x * xs1 + acc[i][n][2] + w121 * bv.x;
            o1.y = xb.y * xs1 + acc[i][n][3] + w121 * bv.y;
            *(float2*)&out[(size_t)r0 * Hd + h] = o0;
            *(float2*)&out[(size_t)(r0 + 8) * Hd + h] = o1;
        }
    }
}

// ---------------- launch ------------------------------------------------------
extern "C" void kernel_launch(void* const* d_in, const int* in_sizes, int n_in,
                              void* d_out, int out_size) {
    const float* x   = (const float*)d_in[0];
    const int*   dm  = (const int*)d_in[1];
    const float* gw1 = (const float*)d_in[2];
    const float* gb1 = (const float*)d_in[3];
    const float* gw2 = (const float*)d_in[4];
    const float* gb2 = (const float*)d_in[5];
    const float* sb  = (const float*)d_in[6];
    const float* bb  = (const float*)d_in[7];
    const float* si  = (const float*)d_in[8];
    const float* bi  = (const float*)d_in[9];
    const float* aw1 = (const float*)d_in[10];
    const float* ab1 = (const float*)d_in[11];
    const float* aw2 = (const float*)d_in[12];
    const float* ab2 = (const float*)d_in[13];
    float* out = (float*)d_out;

    cudaFuncSetAttribute(k_up, cudaFuncAttributeMaxDynamicSharedMemorySize, UP_SMEM);
    cudaFuncSetAttribute(k_down, cudaFuncAttributeMaxDynamicSharedMemorySize, DN_SMEM);

    k_prep<<<5248, 256>>>(x, dm, gw1, gb1, gw2, gb2, sb, si, bb, bi, aw1, ab1, aw2);
    k_up<<<dim3(Fd / 64, Td / 128), 128, UP_SMEM>>>();
    k_down<<<dim3(Hd / 128, Td / 128), 128, DN_SMEM>>>(x, ab2, out);
}

// round 14
// speedup vs baseline: 1.0739x; 1.0739x over previous
#include <cuda_runtime.h>
#include <cuda_fp16.h>
#include <cstdint>

#define Hd 1024
#define Fd 2048
#define Td 8192

// ---------------- scratch (__device__ globals; no allocs allowed) -------------
__device__ __align__(16) float g_wts[Td * 4];    // w0, w1, w2, w1+w2
__device__ __align__(16) float g_cvec[2][Fd];    // b_d @ ad_w1 + ad_b1
__device__ __align__(16) __half g_xp[(size_t)Td * Hd];      // packed norm(x)
__device__ __align__(16) __half g_Bp[2 * (size_t)Fd * Hd];  // packed W1^T scaled
__device__ __align__(16) __half g_W2p[(size_t)Hd * Fd];     // packed W2^T
__device__ __align__(16) __half g_gp[(size_t)Td * Fd];      // packed activation

// ---------------- PTX helpers -------------------------------------------------
__device__ __forceinline__ uint32_t smem_u32(const void* p) {
    uint32_t a;
    asm("{ .reg .u64 t; cvta.to.shared.u64 t, %1; cvt.u32.u64 %0, t; }"
        : "=r"(a) : "l"(p));
    return a;
}
#define LDSM4(r, a) \
    asm volatile("ldmatrix.sync.aligned.m8n8.x4.shared.b16 {%0,%1,%2,%3}, [%4];" \
                 : "=r"((r)[0]), "=r"((r)[1]), "=r"((r)[2]), "=r"((r)[3]) : "r"(a))
#define MBAR_INIT(a, c)  asm volatile("mbarrier.init.shared.b64 [%0], %1;" :: "r"(a), "r"((uint32_t)(c)) : "memory")
#define MBAR_EXPECT(a, tx) asm volatile("mbarrier.arrive.expect_tx.shared.b64 _, [%0], %1;" :: "r"(a), "r"((uint32_t)(tx)) : "memory")
#define MBAR_WAIT(a, p) do { \
    uint32_t _m = (a), _p = (uint32_t)(p), _d; \
    asm volatile("{\n\t.reg .pred q;\n\tmbarrier.try_wait.parity.acquire.cta.shared::cta.b64 q, [%1], %2;\n\tselp.b32 %0,1,0,q;\n\t}" \
                 : "=r"(_d) : "r"(_m), "r"(_p) : "memory"); \
    if (!_d) { \
        asm volatile("{\n\t.reg .pred q;\n\tLW_%=:\n\tmbarrier.try_wait.parity.acquire.cta.shared::cta.b64 q, [%0], %1, 0x989680;\n\t@q bra.uni LD_%=;\n\tbra.uni LW_%=;\n\tLD_%=:\n\t}" \
                     :: "r"(_m), "r"(_p) : "memory"); \
    } } while (0)
#define BULK(dst, src, sz, mb) \
    asm volatile("cp.async.bulk.shared::cluster.global.mbarrier::complete_tx::bytes [%0], [%1], %2, [%3];" \
                 :: "r"(dst), "l"(__cvta_generic_to_global(src)), "r"((uint32_t)(sz)), "r"(mb) : "memory")

__device__ __forceinline__ void mma_f16(float* d, const uint32_t* a,
                                        uint32_t b0, uint32_t b1) {
    asm volatile(
        "mma.sync.aligned.m16n8k16.row.col.f32.f16.f16.f32 "
        "{%0,%1,%2,%3}, {%4,%5,%6,%7}, {%8,%9}, {%0,%1,%2,%3};"
        : "+f"(d[0]), "+f"(d[1]), "+f"(d[2]), "+f"(d[3])
        : "r"(a[0]), "r"(a[1]), "r"(a[2]), "r"(a[3]), "r"(b0), "r"(b1));
}

__device__ __forceinline__ uint32_t hpack(float a, float b) {
    const __half2 h = __floats2half2_rn(a, b);
    return *(const uint32_t*)&h;
}
__device__ __forceinline__ size_t gp_off(int m, int f) {   // halves offset in g_gp
    return ((size_t)((m >> 7) * 64 + (f >> 5))) * 4096 +
           ((f >> 3) & 3) * 1024 + (m & 127) * 8 + (f & 7);
}

// ---------------- fused prep: trans1 | trans2 | prepc | gate ------------------
// Smem-free transposes: per thread, 8 coalesced row reads -> 1 coalesced uint4
// write (the packed layout's innermost 8 halves run along the source-row dim).
// block ranges (all 256 thr): [0,1024) trans1, [1024,2048) trans2,
//                             [2048,2176) prepc, [2176,3200) gate.
__global__ void k_prep(const float* __restrict__ x, const int* __restrict__ dm,
                       const float* __restrict__ gw1, const float* __restrict__ gb1,
                       const float* __restrict__ gw2, const float* __restrict__ gb2,
                       const float* __restrict__ sb, const float* __restrict__ si,
                       const float* __restrict__ bb, const float* __restrict__ bi,
                       const float* __restrict__ aw1, const float* __restrict__ ab1,
                       const float* __restrict__ aw2) {
    __shared__ float sh[8][32];
    const int b = blockIdx.x;
    const int tid = threadIdx.x;

    if (b < 1024) {                    // ---- trans1: W1 -> packed, 2 domains
        const int h0 = (b >> 3) * 8;                 // h-octet base
        const int f = (b & 7) * 256 + tid;           // 0..2047, lanes contiguous
        float w[8];
        #pragma unroll
        for (int q = 0; q < 8; q++)
            w[q] = aw1[(size_t)(h0 + q) * Fd + f];   // coalesced 128B per q
        uint32_t pb[4], pi[4];
        #pragma unroll
        for (int q = 0; q < 4; q++) {
            const float b0 = __ldg(sb + h0 + 2 * q), b1 = __ldg(sb + h0 + 2 * q + 1);
            const float i0 = __ldg(si + h0 + 2 * q), i1 = __ldg(si + h0 + 2 * q + 1);
            pb[q] = hpack(w[2 * q] * b0, w[2 * q + 1] * b1);
            pi[q] = hpack(w[2 * q] * i0, w[2 * q + 1] * i1);
        }
        const size_t off = ((size_t)((f >> 6) * 32 + (h0 >> 5))) * 2048 +
                           ((h0 >> 3) & 3) * 512 + (f & 63) * 8;
        *(uint4*)(g_Bp + off) = *(uint4*)pb;                        // coalesced
        *(uint4*)(g_Bp + (size_t)Fd * Hd + off) = *(uint4*)pi;
    } else if (b < 2048) {             // ---- trans2: W2 -> packed
        const int bb2 = b - 1024;
        const int f0 = (bb2 >> 2) * 8;               // f-octet base
        const int h = (bb2 & 3) * 256 + tid;         // 0..1023, lanes contiguous
        float w[8];
        #pragma unroll
        for (int q = 0; q < 8; q++)
            w[q] = aw2[(size_t)(f0 + q) * Hd + h];   // coalesced 128B per q
        uint32_t pk[4];
        #pragma unroll
        for (int q = 0; q < 4; q++)
            pk[q] = hpack(w[2 * q], w[2 * q + 1]);
        const size_t off = ((size_t)((h >> 7) * 64 + (f0 >> 5))) * 4096 +
                           ((f0 >> 3) & 3) * 1024 + (h & 127) * 8;
        *(uint4*)(g_W2p + off) = *(uint4*)pk;                       // coalesced
    } else if (b < 2176) {             // ---- prepc: c_d = b_d @ W1 + ad_b1
        const int lane32 = tid & 31;
        const int ks = tid >> 5;
        const int i = (b - 2048) * 32 + lane32;      // 0..4095
        const int d = i >> 11;
        const int f = i & (Fd - 1);
        const float* bv = d ? bi : bb;
        float acc = 0.f;
        #pragma unroll 8
        for (int h = ks * 128; h < ks * 128 + 128; h++)
            acc = fmaf(__ldg(bv + h), aw1[(size_t)h * Fd + f], acc);
        sh[ks][lane32] = acc;
        __syncthreads();
        if (ks == 0) {
            float s = sh[0][lane32];
            #pragma unroll
            for (int q = 1; q < 8; q++) s += sh[q][lane32];
            g_cvec[d][f] = ab1[f] + s;
        }
    } else {                           // ---- gate: LN stats + weights + xp
        const int t = (b - 2176) * 8 + (tid >> 5);
        const int lane = tid & 31;
        const float* xr = x + (size_t)t * Hd;

        float4 xv[8];
        float s = 0.f, ss = 0.f, a0 = 0.f, a1 = 0.f, a2 = 0.f, a3 = 0.f;
        #pragma unroll
        for (int it = 0; it < 8; it++) {
            const int h = lane * 4 + it * 128;
            xv[it] = *(const float4*)(xr + h);
            const float4 v = xv[it];
            s  += v.x + v.y + v.z + v.w;
            ss += v.x * v.x + v.y * v.y + v.z * v.z + v.w * v.w;
            const float4* gw = (const float4*)(gw1 + h * 4);
            float4 w0r = gw[0], w1r = gw[1], w2r = gw[2], w3r = gw[3];
            a0 += v.x * w0r.x + v.y * w1r.x + v.z * w2r.x + v.w * w3r.x;
            a1 += v.x * w0r.y + v.y * w1r.y + v.z * w2r.y + v.w * w3r.y;
            a2 += v.x * w0r.z + v.y * w1r.z + v.z * w2r.z + v.w * w3r.z;
            a3 += v.x * w0r.w + v.y * w1r.w + v.z * w2r.w + v.w * w3r.w;
        }
        #pragma unroll
        for (int o = 16; o; o >>= 1) {
            s  += __shfl_xor_sync(0xffffffffu, s, o);
            ss += __shfl_xor_sync(0xffffffffu, ss, o);
            a0 += __shfl_xor_sync(0xffffffffu, a0, o);
            a1 += __shfl_xor_sync(0xffffffffu, a1, o);
            a2 += __shfl_xor_sync(0xffffffffu, a2, o);
            a3 += __shfl_xor_sync(0xffffffffu, a3, o);
        }
        const float mean = s * (1.f / Hd);
        const float var = ss * (1.f / Hd) - mean * mean;
        const float rstd = rsqrtf(var + 1e-6f);

        const int mb = t >> 7, r = t & 127;
        #pragma unroll
        for (int it = 0; it < 8; it++) {
            const int k = lane * 4 + it * 128;
            const int c = k >> 5, kb = (k >> 3) & 3, wi = k & 7;
            const float4 v = xv[it];
            uint2 o;
            o.x = hpack((v.x - mean) * rstd, (v.y - mean) * rstd);
            o.y = hpack((v.z - mean) * rstd, (v.w - mean) * rstd);
            *(uint2*)(g_xp + ((size_t)(mb * 32 + c)) * 4096 + kb * 1024 + r * 8 + wi) = o;
        }

        if (lane == 0) {
            float hv[4] = {fmaxf(a0 + gb1[0], 0.f), fmaxf(a1 + gb1[1], 0.f),
                           fmaxf(a2 + gb1[2], 0.f), fmaxf(a3 + gb1[3], 0.f)};
            float lg[4];
            #pragma unroll
            for (int e = 0; e < 4; e++) {
                float acc = gb2[e];
                #pragma unroll
                for (int d = 0; d < 4; d++) acc += hv[d] * gw2[d * 4 + e];
                if (dm[e] == 0) acc = -1e9f;
                lg[e] = acc;
            }
            const float mx = fmaxf(fmaxf(lg[0], lg[1]), fmaxf(lg[2], lg[3]));
            const float e0 = expf(lg[0] - mx), e1 = expf(lg[1] - mx);
            const float e2 = expf(lg[2] - mx), e3 = expf(lg[3] - mx);
            const float inv = 1.f / (e0 + e1 + e2 + e3);
            g_wts[4 * t + 0] = e0 * inv;
            g_wts[4 * t + 1] = e1 * inv;
            g_wts[4 * t + 2] = e2 * inv;
            g_wts[4 * t + 3] = (e1 + e2) * inv;
        }
    }
}

// ---------------- kernel: up GEMM (TMA bulk, warp 64x64, 128 thr) -------------
// CTA 128m x 64f x 2dom, 4 warps: dom = wid>>1, mw = (wid&1)*64; warp 64m x 64f.
// Stage (32KB): A 16K | B_book 8K | B_iwslt 8K; 3 stages + mbarriers.
#define UP_SMEM  98368
#define UP_STAGE 32768
__global__ void __launch_bounds__(128, 2) k_up() {
    extern __shared__ char smem[];
    const uint32_t sm = smem_u32(smem);
    const uint32_t mbb = sm + 98304;
    const int tid = threadIdx.x, lane = tid & 31, wid = tid >> 5;
    const int mb = blockIdx.y, nb = blockIdx.x;
    const int m0 = mb * 128, n0 = nb * 64;
    const int dom = wid >> 1, mw = (wid & 1) * 64;
    const int aRow = lane & 15, aK = lane >> 4;
    const int bRow = (lane & 7) + ((lane >> 4) << 3), bK = (lane >> 3) & 1;

    float acc[4][8][4];
    #pragma unroll
    for (int i = 0; i < 4; i++)
        #pragma unroll
        for (int n = 0; n < 8; n++)
            #pragma unroll
            for (int q = 0; q < 4; q++) acc[i][n][q] = 0.f;

    auto issue = [&](int c, int st) {
        const uint32_t mbar = mbb + st * 8;
        const uint32_t dst = sm + st * UP_STAGE;
        MBAR_EXPECT(mbar, 32768);
        BULK(dst, g_xp + ((size_t)(mb * 32 + c * 2)) * 4096, 16384, mbar);
        BULK(dst + 16384, g_Bp + ((size_t)(nb * 32 + c * 2)) * 2048, 8192, mbar);
        BULK(dst + 24576, g_Bp + (size_t)Fd * Hd + ((size_t)(nb * 32 + c * 2)) * 2048, 8192, mbar);
    };

    if (tid == 0) {
        #pragma unroll
        for (int st = 0; st < 3; st++) MBAR_INIT(mbb + st * 8, 1);
    }
    __syncthreads();
    if (tid == 0) { issue(0, 0); issue(1, 1); }

    int st = 0, ph = 0, st2 = 2;
    #pragma unroll 1
    for (int c = 0; c < 16; c++) {
        __syncthreads();                     // stage st2 free for reuse
        if (tid == 0 && c + 2 < 16) issue(c + 2, st2);
        MBAR_WAIT(mbb + st * 8, ph);
        const uint32_t smA = sm + st * UP_STAGE;
        const uint32_t smB = smA + 16384 + dom * 8192;
        #pragma unroll
        for (int j = 0; j < 4; j++) {
            uint32_t a[4][4];
            const uint32_t aBase = smA + (j >> 1) * 8192 +
                (((2 * (j & 1) + aK) << 7) + mw + aRow) * 16;
            #pragma unroll
            for (int i = 0; i < 4; i++) LDSM4(a[i], aBase + i * 256);
            uint32_t b[4][4];
            const uint32_t bBase = smB + (j >> 1) * 4096 +
                (((2 * (j & 1) + bK) << 6) + bRow) * 16;
            #pragma unroll
            for (int nbb = 0; nbb < 4; nbb++) LDSM4(b[nbb], bBase + nbb * 256);
            #pragma unroll
            for (int i = 0; i < 4; i++)
                #pragma unroll
                for (int nbb = 0; nbb < 4; nbb++) {
                    mma_f16(acc[i][2 * nbb + 0], a[i], b[nbb][0], b[nbb][1]);
                    mma_f16(acc[i][2 * nbb + 1], a[i], b[nbb][2], b[nbb][3]);
                }
        }
        if (++st2 == 3) st2 = 0;
        if (++st == 3) { st = 0; ph ^= 1; }
    }

    // --- epilogue: dom1 -> smem (w2*relu), dom0 combines, writes packed g -----
    __syncthreads();
    const int g = lane >> 2, tq = lane & 3;
    float* ex = (float*)smem;               // [128][68] f32 = 34.8KB
    if (dom == 1) {
        #pragma unroll
        for (int i = 0; i < 4; i++) {
            const int r = mw + 16 * i + g;
            const float w2a = g_wts[4 * (m0 + r) + 2];
            const float w2b = g_wts[4 * (m0 + r + 8) + 2];
            #pragma unroll
            for (int n = 0; n < 8; n++) {
                const int col = 8 * n + 2 * tq;
                const float cv0 = g_cvec[1][n0 + col], cv1 = g_cvec[1][n0 + col + 1];
                float2 v0, v1;
                v0.x = w2a * fmaxf(acc[i][n][0] + cv0, 0.f);
                v0.y = w2a * fmaxf(acc[i][n][1] + cv1, 0.f);
                v1.x = w2b * fmaxf(acc[i][n][2] + cv0, 0.f);
                v1.y = w2b * fmaxf(acc[i][n][3] + cv1, 0.f);
                *(float2*)(ex + (size_t)r * 68 + col) = v0;
                *(float2*)(ex + (size_t)(r + 8) * 68 + col) = v1;
            }
        }
    }
    __syncthreads();
    if (dom == 0) {
        #pragma unroll
        for (int i = 0; i < 4; i++) {
            const int r = mw + 16 * i + g;
            const float w1a = g_wts[4 * (m0 + r) + 1];
            const float w1b = g_wts[4 * (m0 + r + 8) + 1];
            #pragma unroll
            for (int n = 0; n < 8; n++) {
                const int col = 8 * n + 2 * tq;
                const int fg = n0 + col;
                const float cv0 = g_cvec[0][fg], cv1 = g_cvec[0][fg + 1];
                const float2 s0 = *(const float2*)(ex + (size_t)r * 68 + col);
                const float2 s1 = *(const float2*)(ex + (size_t)(r + 8) * 68 + col);
                const float g0 = w1a * fmaxf(acc[i][n][0] + cv0, 0.f) + s0.x;
                const float g1 = w1a * fmaxf(acc[i][n][1] + cv1, 0.f) + s0.y;
                const float g2 = w1b * fmaxf(acc[i][n][2] + cv0, 0.f) + s1.x;
                const float g3 = w1b * fmaxf(acc[i][n][3] + cv1, 0.f) + s1.y;
                *(uint32_t*)(g_gp + gp_off(m0 + r, fg)) = hpack(g0, g1);
                *(uint32_t*)(g_gp + gp_off(m0 + r + 8, fg)) = hpack(g2, g3);
            }
        }
    }
}

// ---------------- kernel: down GEMM (TMA bulk, warp 64x64, 128 thr) -----------
// CTA 128m x 128h, 4 warps 2m x 2n, warp 64m x 64h.
// Stage (32KB): A 16K | B 16K; 3 stages + mbarriers.
#define DN_SMEM  98368
#define DN_STAGE 32768
__global__ void __launch_bounds__(128, 2) k_down(const float* __restrict__ x,
                                                 const float* __restrict__ b2,
                                                 float* __restrict__ out) {
    extern __shared__ char smem[];
    const uint32_t sm = smem_u32(smem);
    const uint32_t mbb = sm + 98304;
    const int tid = threadIdx.x, lane = tid & 31, wid = tid >> 5;
    const int mb = blockIdx.y, hb = blockIdx.x;
    const int m0 = mb * 128, n0 = hb * 128;
    const int mw = (wid & 1) * 64, nw = (wid >> 1) * 64;
    const int aRow = lane & 15, aK = lane >> 4;
    const int bRow = (lane & 7) + ((lane >> 4) << 3), bK = (lane >> 3) & 1;

    float acc[4][8][4];
    #pragma unroll
    for (int i = 0; i < 4; i++)
        #pragma unroll
        for (int n = 0; n < 8; n++)
            #pragma unroll
            for (int q = 0; q < 4; q++) acc[i][n][q] = 0.f;

    auto issue = [&](int c, int st) {
        const uint32_t mbar = mbb + st * 8;
        const uint32_t dst = sm + st * DN_STAGE;
        MBAR_EXPECT(mbar, 32768);
        BULK(dst, g_gp + ((size_t)(mb * 64 + c * 2)) * 4096, 16384, mbar);
        BULK(dst + 16384, g_W2p + ((size_t)(hb * 64 + c * 2)) * 4096, 16384, mbar);
    };

    if (tid == 0) {
        #pragma unroll
        for (int st = 0; st < 3; st++) MBAR_INIT(mbb + st * 8, 1);
    }
    __syncthreads();
    if (tid == 0) { issue(0, 0); issue(1, 1); }

    int st = 0, ph = 0, st2 = 2;
    #pragma unroll 1
    for (int c = 0; c < 32; c++) {
        __syncthreads();
        if (tid == 0 && c + 2 < 32) issue(c + 2, st2);
        MBAR_WAIT(mbb + st * 8, ph);
        const uint32_t smA = sm + st * DN_STAGE;
        const uint32_t smB = smA + 16384;
        #pragma unroll
        for (int j = 0; j < 4; j++) {
            uint32_t a[4][4];
            const uint32_t aBase = smA + (j >> 1) * 8192 +
                (((2 * (j & 1) + aK) << 7) + mw + aRow) * 16;
            #pragma unroll
            for (int i = 0; i < 4; i++) LDSM4(a[i], aBase + i * 256);
            uint32_t b[4][4];
            const uint32_t bBase = smB + (j >> 1) * 8192 +
                (((2 * (j & 1) + bK) << 7) + nw + bRow) * 16;
            #pragma unroll
            for (int nbb = 0; nbb < 4; nbb++) LDSM4(b[nbb], bBase + nbb * 256);
            #pragma unroll
            for (int i = 0; i < 4; i++)
                #pragma unroll
                for (int nbb = 0; nbb < 4; nbb++) {
                    mma_f16(acc[i][2 * nbb + 0], a[i], b[nbb][0], b[nbb][1]);
                    mma_f16(acc[i][2 * nbb + 1], a[i], b[nbb][2], b[nbb][3]);
                }
        }
        if (++st2 == 3) st2 = 0;
        if (++st == 3) { st = 0; ph ^= 1; }
    }

    // --- epilogue: out = x*(1+w0) + acc + (w1+w2)*b2 --------------------------
    const int g = lane >> 2, tq = lane & 3;
    #pragma unroll
    for (int i = 0; i < 4; i++) {
        const int r0 = m0 + mw + 16 * i + g;
        const float4 wv0 = *(const float4*)&g_wts[4 * r0];
        const float4 wv1 = *(const float4*)&g_wts[4 * (r0 + 8)];
        const float xs0 = 1.f + wv0.x, w120 = wv0.w;
        const float xs1 = 1.f + wv1.x, w121 = wv1.w;
        #pragma unroll
        for (int n = 0; n < 8; n++) {
            const int h = n0 + nw + 8 * n + 2 * tq;
            const float2 xa = *(const float2*)&x[(size_t)r0 * Hd + h];
            const float2 xb = *(const float2*)&x[(size_t)(r0 + 8) * Hd + h];
            const float2 bv = *(const float2*)&b2[h];
            float2 o0, o1;
            o0.x = xa.x * xs0 + acc[i][n][0] + w120 * bv.x;
            o0.y = xa.y * xs0 + acc[i][n][1] + w120 * bv.y;
            o1.x = xb.x * xs1 + acc[i][n][2] + w121 * bv.x;
            o1.y = xb.y * xs1 + acc[i][n][3] + w121 * bv.y;
            *(float2*)&out[(size_t)r0 * Hd + h] = o0;
            *(float2*)&out[(size_t)(r0 + 8) * Hd + h] = o1;
        }
    }
}

// ---------------- launch ------------------------------------------------------
extern "C" void kernel_launch(void* const* d_in, const int* in_sizes, int n_in,
                              void* d_out, int out_size) {
    const float* x   = (const float*)d_in[0];
    const int*   dm  = (const int*)d_in[1];
    const float* gw1 = (const float*)d_in[2];
    const float* gb1 = (const float*)d_in[3];
    const float* gw2 = (const float*)d_in[4];
    const float* gb2 = (const float*)d_in[5];
    const float* sb  = (const float*)d_in[6];
    const float* bb  = (const float*)d_in[7];
    const float* si  = (const float*)d_in[8];
    const float* bi  = (const float*)d_in[9];
    const float* aw1 = (const float*)d_in[10];
    const float* ab1 = (const float*)d_in[11];
    const float* aw2 = (const float*)d_in[12];
    const float* ab2 = (const float*)d_in[13];
    float* out = (float*)d_out;

    cudaFuncSetAttribute(k_up, cudaFuncAttributeMaxDynamicSharedMemorySize, UP_SMEM);
    cudaFuncSetAttribute(k_down, cudaFuncAttributeMaxDynamicSharedMemorySize, DN_SMEM);

    k_prep<<<3200, 256>>>(x, dm, gw1, gb1, gw2, gb2, sb, si, bb, bi, aw1, ab1, aw2);
    k_up<<<dim3(Fd / 64, Td / 128), 128, UP_SMEM>>>();
    k_down<<<dim3(Hd / 128, Td / 128), 128, DN_SMEM>>>(x, ab2, out);
}

// round 16
// speedup vs baseline: 1.1726x; 1.0919x over previous
#include <cuda_runtime.h>
#include <cuda_fp16.h>
#include <cstdint>

#define Hd 1024
#define Fd 2048
#define Td 8192

// ---------------- scratch (__device__ globals; no allocs allowed) -------------
__device__ __align__(16) float g_wts[Td * 4];    // w0, w1, w2, w1+w2
__device__ __align__(16) float g_cvec[2][Fd];    // b_d @ ad_w1 + ad_b1
__device__ __align__(16) __half g_xp[(size_t)Td * Hd];      // packed norm(x)
__device__ __align__(16) __half g_Bp[2 * (size_t)Fd * Hd];  // packed W1^T scaled
__device__ __align__(16) __half g_W2p[(size_t)Hd * Fd];     // packed W2^T
__device__ __align__(16) __half g_gp[(size_t)Td * Fd];      // packed activation

// ---------------- PTX helpers -------------------------------------------------
__device__ __forceinline__ uint32_t smem_u32(const void* p) {
    uint32_t a;
    asm("{ .reg .u64 t; cvta.to.shared.u64 t, %1; cvt.u32.u64 %0, t; }"
        : "=r"(a) : "l"(p));
    return a;
}
#define LDSM4(r, a) \
    asm volatile("ldmatrix.sync.aligned.m8n8.x4.shared.b16 {%0,%1,%2,%3}, [%4];" \
                 : "=r"((r)[0]), "=r"((r)[1]), "=r"((r)[2]), "=r"((r)[3]) : "r"(a))
#define MBAR_INIT(a, c)  asm volatile("mbarrier.init.shared.b64 [%0], %1;" :: "r"(a), "r"((uint32_t)(c)) : "memory")
#define MBAR_EXPECT(a, tx) asm volatile("mbarrier.arrive.expect_tx.shared.b64 _, [%0], %1;" :: "r"(a), "r"((uint32_t)(tx)) : "memory")
#define MBAR_WAIT(a, p) do { \
    uint32_t _m = (a), _p = (uint32_t)(p), _d; \
    asm volatile("{\n\t.reg .pred q;\n\tmbarrier.try_wait.parity.acquire.cta.shared::cta.b64 q, [%1], %2;\n\tselp.b32 %0,1,0,q;\n\t}" \
                 : "=r"(_d) : "r"(_m), "r"(_p) : "memory"); \
    if (!_d) { \
        asm volatile("{\n\t.reg .pred q;\n\tLW_%=:\n\tmbarrier.try_wait.parity.acquire.cta.shared::cta.b64 q, [%0], %1, 0x989680;\n\t@q bra.uni LD_%=;\n\tbra.uni LW_%=;\n\tLD_%=:\n\t}" \
                     :: "r"(_m), "r"(_p) : "memory"); \
    } } while (0)
#define BULK(dst, src, sz, mb) \
    asm volatile("cp.async.bulk.shared::cluster.global.mbarrier::complete_tx::bytes [%0], [%1], %2, [%3];" \
                 :: "r"(dst), "l"(__cvta_generic_to_global(src)), "r"((uint32_t)(sz)), "r"(mb) : "memory")

__device__ __forceinline__ void mma_f16(float* d, const uint32_t* a,
                                        uint32_t b0, uint32_t b1) {
    asm volatile(
        "mma.sync.aligned.m16n8k16.row.col.f32.f16.f16.f32 "
        "{%0,%1,%2,%3}, {%4,%5,%6,%7}, {%8,%9}, {%0,%1,%2,%3};"
        : "+f"(d[0]), "+f"(d[1]), "+f"(d[2]), "+f"(d[3])
        : "r"(a[0]), "r"(a[1]), "r"(a[2]), "r"(a[3]), "r"(b0), "r"(b1));
}

__device__ __forceinline__ uint32_t hpack(float a, float b) {
    const __half2 h = __floats2half2_rn(a, b);
    return *(const uint32_t*)&h;
}
__device__ __forceinline__ size_t gp_off(int m, int f) {   // halves offset in g_gp
    return ((size_t)((m >> 7) * 64 + (f >> 5))) * 4096 +
           ((f >> 3) & 3) * 1024 + (m & 127) * 8 + (f & 7);
}

// ---------------- fused prep: trans1 | trans2 | prepc | gate ------------------
// block ranges (all 256 thr): [0,1024) trans1, [1024,2048) trans2,
//                             [2048,2176) prepc, [2176,3200) gate.
// Gate xp stores go through a padded smem bounce -> fully coalesced 128B runs.
__global__ void k_prep(const float* __restrict__ x, const int* __restrict__ dm,
                       const float* __restrict__ gw1, const float* __restrict__ gb1,
                       const float* __restrict__ gw2, const float* __restrict__ gb2,
                       const float* __restrict__ sb, const float* __restrict__ si,
                       const float* __restrict__ bb, const float* __restrict__ bi,
                       const float* __restrict__ aw1, const float* __restrict__ ab1,
                       const float* __restrict__ aw2) {
    // gate staging: 128 regions x 72 halves (pad 8) = 18432 B; prepc reuses it.
    __shared__ __align__(16) __half shb[128 * 72];
    const int b = blockIdx.x;
    const int tid = threadIdx.x;

    if (b < 1024) {                    // ---- trans1: W1 -> packed, 2 domains
        const int h0 = (b >> 3) * 8;                 // h-octet base
        const int f = (b & 7) * 256 + tid;           // lanes contiguous
        float w[8];
        #pragma unroll
        for (int q = 0; q < 8; q++)
            w[q] = aw1[(size_t)(h0 + q) * Fd + f];   // coalesced 128B per q
        uint32_t pb[4], pi[4];
        #pragma unroll
        for (int q = 0; q < 4; q++) {
            const float b0 = __ldg(sb + h0 + 2 * q), b1 = __ldg(sb + h0 + 2 * q + 1);
            const float i0 = __ldg(si + h0 + 2 * q), i1 = __ldg(si + h0 + 2 * q + 1);
            pb[q] = hpack(w[2 * q] * b0, w[2 * q + 1] * b1);
            pi[q] = hpack(w[2 * q] * i0, w[2 * q + 1] * i1);
        }
        const size_t off = ((size_t)((f >> 6) * 32 + (h0 >> 5))) * 2048 +
                           ((h0 >> 3) & 3) * 512 + (f & 63) * 8;
        *(uint4*)(g_Bp + off) = *(uint4*)pb;                        // coalesced
        *(uint4*)(g_Bp + (size_t)Fd * Hd + off) = *(uint4*)pi;
    } else if (b < 2048) {             // ---- trans2: W2 -> packed
        const int bb2 = b - 1024;
        const int f0 = (bb2 >> 2) * 8;               // f-octet base
        const int h = (bb2 & 3) * 256 + tid;         // lanes contiguous
        float w[8];
        #pragma unroll
        for (int q = 0; q < 8; q++)
            w[q] = aw2[(size_t)(f0 + q) * Hd + h];   // coalesced 128B per q
        uint32_t pk[4];
        #pragma unroll
        for (int q = 0; q < 4; q++)
            pk[q] = hpack(w[2 * q], w[2 * q + 1]);
        const size_t off = ((size_t)((h >> 7) * 64 + (f0 >> 5))) * 4096 +
                           ((f0 >> 3) & 3) * 1024 + (h & 127) * 8;
        *(uint4*)(g_W2p + off) = *(uint4*)pk;                       // coalesced
    } else if (b < 2176) {             // ---- prepc: c_d = b_d @ W1 + ad_b1
        float* sh = (float*)shb;                     // [8][32]
        const int lane32 = tid & 31;
        const int ks = tid >> 5;
        const int i = (b - 2048) * 32 + lane32;      // 0..4095
        const int d = i >> 11;
        const int f = i & (Fd - 1);
        const float* bv = d ? bi : bb;
        float acc = 0.f;
        #pragma unroll 8
        for (int h = ks * 128; h < ks * 128 + 128; h++)
            acc = fmaf(__ldg(bv + h), aw1[(size_t)h * Fd + f], acc);
        sh[ks * 32 + lane32] = acc;
        __syncthreads();
        if (ks == 0) {
            float s = sh[lane32];
            #pragma unroll
            for (int q = 1; q < 8; q++) s += sh[q * 32 + lane32];
            g_cvec[d][f] = ab1[f] + s;
        }
    } else {                           // ---- gate: LN stats + weights + xp
        const int rl = tid >> 5;                     // warp = local token 0..7
        const int t = (b - 2176) * 8 + rl;
        const int lane = tid & 31;
        const float* xr = x + (size_t)t * Hd;

        float4 xv[8];
        float s = 0.f, ss = 0.f, a0 = 0.f, a1 = 0.f, a2 = 0.f, a3 = 0.f;
        #pragma unroll
        for (int it = 0; it < 8; it++) {
            const int h = lane * 4 + it * 128;
            xv[it] = *(const float4*)(xr + h);
            const float4 v = xv[it];
            s  += v.x + v.y + v.z + v.w;
            ss += v.x * v.x + v.y * v.y + v.z * v.z + v.w * v.w;
            const float4* gw = (const float4*)(gw1 + h * 4);
            float4 w0r = gw[0], w1r = gw[1], w2r = gw[2], w3r = gw[3];
            a0 += v.x * w0r.x + v.y * w1r.x + v.z * w2r.x + v.w * w3r.x;
            a1 += v.x * w0r.y + v.y * w1r.y + v.z * w2r.y + v.w * w3r.y;
            a2 += v.x * w0r.z + v.y * w1r.z + v.z * w2r.z + v.w * w3r.z;
            a3 += v.x * w0r.w + v.y * w1r.w + v.z * w2r.w + v.w * w3r.w;
        }
        #pragma unroll
        for (int o = 16; o; o >>= 1) {
            s  += __shfl_xor_sync(0xffffffffu, s, o);
            ss += __shfl_xor_sync(0xffffffffu, ss, o);
            a0 += __shfl_xor_sync(0xffffffffu, a0, o);
            a1 += __shfl_xor_sync(0xffffffffu, a1, o);
            a2 += __shfl_xor_sync(0xffffffffu, a2, o);
            a3 += __shfl_xor_sync(0xffffffffu, a3, o);
        }
        const float mean = s * (1.f / Hd);
        const float var = ss * (1.f / Hd) - mean * mean;
        const float rstd = rsqrtf(var + 1e-6f);

        // stage normalized fp16 in smem: [region=k>>3][rl][wi=k&7], 72-half rows
        #pragma unroll
        for (int it = 0; it < 8; it++) {
            const int k = lane * 4 + it * 128;
            const int region = k >> 3, wi = k & 7;
            const float4 v = xv[it];
            uint2 o;
            o.x = hpack((v.x - mean) * rstd, (v.y - mean) * rstd);
            o.y = hpack((v.z - mean) * rstd, (v.w - mean) * rstd);
            *(uint2*)(shb + region * 72 + rl * 8 + wi) = o;
        }
        __syncthreads();
        // block-wide coalesced stores: 8 consecutive threads = 128B run
        const int mb = t >> 7;
        const int r0 = ((b - 2176) * 8) & 127;
        #pragma unroll
        for (int rep = 0; rep < 4; rep++) {
            const int u = tid + rep * 256;           // 0..1023
            const int region = u >> 3, rr = u & 7;
            const uint4 v = *(const uint4*)(shb + region * 72 + rr * 8);
            const int c = region >> 2, kb = region & 3;
            *(uint4*)(g_xp + ((size_t)(mb * 32 + c)) * 4096 + kb * 1024 +
                      (r0 + rr) * 8) = v;
        }

        if (lane == 0) {
            float hv[4] = {fmaxf(a0 + gb1[0], 0.f), fmaxf(a1 + gb1[1], 0.f),
                           fmaxf(a2 + gb1[2], 0.f), fmaxf(a3 + gb1[3], 0.f)};
            float lg[4];
            #pragma unroll
            for (int e = 0; e < 4; e++) {
                float acc = gb2[e];
                #pragma unroll
                for (int d = 0; d < 4; d++) acc += hv[d] * gw2[d * 4 + e];
                if (dm[e] == 0) acc = -1e9f;
                lg[e] = acc;
            }
            const float mx = fmaxf(fmaxf(lg[0], lg[1]), fmaxf(lg[2], lg[3]));
            const float e0 = expf(lg[0] - mx), e1 = expf(lg[1] - mx);
            const float e2 = expf(lg[2] - mx), e3 = expf(lg[3] - mx);
            const float inv = 1.f / (e0 + e1 + e2 + e3);
            g_wts[4 * t + 0] = e0 * inv;
            g_wts[4 * t + 1] = e1 * inv;
            g_wts[4 * t + 2] = e2 * inv;
            g_wts[4 * t + 3] = (e1 + e2) * inv;
        }
    }
}

// ---------------- kernel: up GEMM (TMA bulk, 2-stage, 3 CTAs/SM) --------------
// CTA 128m x 64f x 2dom, 4 warps: dom = wid>>1, mw = (wid&1)*64; warp 64m x 64f.
// Stage (32KB): A 16K | B_book 8K | B_iwslt 8K; 2 stages + mbarriers = 65600.
#define UP_SMEM  65600
#define UP_STAGE 32768
__global__ void __launch_bounds__(128, 3) k_up() {
    extern __shared__ char smem[];
    const uint32_t sm = smem_u32(smem);
    const uint32_t mbb = sm + 65536;
    const int tid = threadIdx.x, lane = tid & 31, wid = tid >> 5;
    const int mb = blockIdx.y, nb = blockIdx.x;
    const int m0 = mb * 128, n0 = nb * 64;
    const int dom = wid >> 1, mw = (wid & 1) * 64;
    const int aRow = lane & 15, aK = lane >> 4;
    const int bRow = (lane & 7) + ((lane >> 4) << 3), bK = (lane >> 3) & 1;

    float acc[4][8][4];
    #pragma unroll
    for (int i = 0; i < 4; i++)
        #pragma unroll
        for (int n = 0; n < 8; n++)
            #pragma unroll
            for (int q = 0; q < 4; q++) acc[i][n][q] = 0.f;

    auto issue = [&](int c, int st) {
        const uint32_t mbar = mbb + st * 8;
        const uint32_t dst = sm + st * UP_STAGE;
        MBAR_EXPECT(mbar, 32768);
        BULK(dst, g_xp + ((size_t)(mb * 32 + c * 2)) * 4096, 16384, mbar);
        BULK(dst + 16384, g_Bp + ((size_t)(nb * 32 + c * 2)) * 2048, 8192, mbar);
        BULK(dst + 24576, g_Bp + (size_t)Fd * Hd + ((size_t)(nb * 32 + c * 2)) * 2048, 8192, mbar);
    };

    if (tid == 0) {
        MBAR_INIT(mbb + 0, 1);
        MBAR_INIT(mbb + 8, 1);
    }
    __syncthreads();
    if (tid == 0) { issue(0, 0); issue(1, 1); }

    #pragma unroll 1
    for (int c = 0; c < 16; c++) {
        const int st = c & 1;
        MBAR_WAIT(mbb + st * 8, (c >> 1) & 1);
        const uint32_t smA = sm + st * UP_STAGE;
        const uint32_t smB = smA + 16384 + dom * 8192;
        #pragma unroll
        for (int j = 0; j < 4; j++) {
            uint32_t a[4][4];
            const uint32_t aBase = smA + (j >> 1) * 8192 +
                (((2 * (j & 1) + aK) << 7) + mw + aRow) * 16;
            #pragma unroll
            for (int i = 0; i < 4; i++) LDSM4(a[i], aBase + i * 256);
            uint32_t b[4][4];
            const uint32_t bBase = smB + (j >> 1) * 4096 +
                (((2 * (j & 1) + bK) << 6) + bRow) * 16;
            #pragma unroll
            for (int nbb = 0; nbb < 4; nbb++) LDSM4(b[nbb], bBase + nbb * 256);
            #pragma unroll
            for (int i = 0; i < 4; i++)
                #pragma unroll
                for (int nbb = 0; nbb < 4; nbb++) {
                    mma_f16(acc[i][2 * nbb + 0], a[i], b[nbb][0], b[nbb][1]);
                    mma_f16(acc[i][2 * nbb + 1], a[i], b[nbb][2], b[nbb][3]);
                }
        }
        __syncthreads();                 // all warps done reading stage st
        if (tid == 0 && c + 2 < 16) issue(c + 2, st);
    }

    // --- epilogue: dom1 -> smem (w2*relu), dom0 combines, writes packed g -----
    const int g = lane >> 2, tq = lane & 3;
    float* ex = (float*)smem;               // [128][68] f32 = 34.8KB
    if (dom == 1) {
        #pragma unroll
        for (int i = 0; i < 4; i++) {
            const int r = mw + 16 * i + g;
            const float w2a = g_wts[4 * (m0 + r) + 2];
            const float w2b = g_wts[4 * (m0 + r + 8) + 2];
            #pragma unroll
            for (int n = 0; n < 8; n++) {
                const int col = 8 * n + 2 * tq;
                const float cv0 = g_cvec[1][n0 + col], cv1 = g_cvec[1][n0 + col + 1];
                float2 v0, v1;
                v0.x = w2a * fmaxf(acc[i][n][0] + cv0, 0.f);
                v0.y = w2a * fmaxf(acc[i][n][1] + cv1, 0.f);
                v1.x = w2b * fmaxf(acc[i][n][2] + cv0, 0.f);
                v1.y = w2b * fmaxf(acc[i][n][3] + cv1, 0.f);
                *(float2*)(ex + (size_t)r * 68 + col) = v0;
                *(float2*)(ex + (size_t)(r + 8) * 68 + col) = v1;
            }
        }
    }
    __syncthreads();
    if (dom == 0) {
        #pragma unroll
        for (int i = 0; i < 4; i++) {
            const int r = mw + 16 * i + g;
            const float w1a = g_wts[4 * (m0 + r) + 1];
            const float w1b = g_wts[4 * (m0 + r + 8) + 1];
            #pragma unroll
            for (int n = 0; n < 8; n++) {
                const int col = 8 * n + 2 * tq;
                const int fg = n0 + col;
                const float cv0 = g_cvec[0][fg], cv1 = g_cvec[0][fg + 1];
                const float2 s0 = *(const float2*)(ex + (size_t)r * 68 + col);
                const float2 s1 = *(const float2*)(ex + (size_t)(r + 8) * 68 + col);
                const float g0 = w1a * fmaxf(acc[i][n][0] + cv0, 0.f) + s0.x;
                const float g1 = w1a * fmaxf(acc[i][n][1] + cv1, 0.f) + s0.y;
                const float g2 = w1b * fmaxf(acc[i][n][2] + cv0, 0.f) + s1.x;
                const float g3 = w1b * fmaxf(acc[i][n][3] + cv1, 0.f) + s1.y;
                *(uint32_t*)(g_gp + gp_off(m0 + r, fg)) = hpack(g0, g1);
                *(uint32_t*)(g_gp + gp_off(m0 + r + 8, fg)) = hpack(g2, g3);
            }
        }
    }
}

// ---------------- kernel: down GEMM (TMA bulk, 2-stage, 3 CTAs/SM) ------------
// CTA 128m x 128h, 4 warps 2m x 2n, warp 64m x 64h.
// Stage (32KB): A 16K | B 16K; 2 stages + mbarriers = 65600.
#define DN_SMEM  65600
#define DN_STAGE 32768
__global__ void __launch_bounds__(128, 3) k_down(const float* __restrict__ x,
                                                 const float* __restrict__ b2,
                                                 float* __restrict__ out) {
    extern __shared__ char smem[];
    const uint32_t sm = smem_u32(smem);
    const uint32_t mbb = sm + 65536;
    const int tid = threadIdx.x, lane = tid & 31, wid = tid >> 5;
    const int mb = blockIdx.y, hb = blockIdx.x;
    const int m0 = mb * 128, n0 = hb * 128;
    const int mw = (wid & 1) * 64, nw = (wid >> 1) * 64;
    const int aRow = lane & 15, aK = lane >> 4;
    const int bRow = (lane & 7) + ((lane >> 4) << 3), bK = (lane >> 3) & 1;

    float acc[4][8][4];
    #pragma unroll
    for (int i = 0; i < 4; i++)
        #pragma unroll
        for (int n = 0; n < 8; n++)
            #pragma unroll
            for (int q = 0; q < 4; q++) acc[i][n][q] = 0.f;

    auto issue = [&](int c, int st) {
        const uint32_t mbar = mbb + st * 8;
        const uint32_t dst = sm + st * DN_STAGE;
        MBAR_EXPECT(mbar, 32768);
        BULK(dst, g_gp + ((size_t)(mb * 64 + c * 2)) * 4096, 16384, mbar);
        BULK(dst + 16384, g_W2p + ((size_t)(hb * 64 + c * 2)) * 4096, 16384, mbar);
    };

    if (tid == 0) {
        MBAR_INIT(mbb + 0, 1);
        MBAR_INIT(mbb + 8, 1);
    }
    __syncthreads();
    if (tid == 0) { issue(0, 0); issue(1, 1); }

    #pragma unroll 1
    for (int c = 0; c < 32; c++) {
        const int st = c & 1;
        MBAR_WAIT(mbb + st * 8, (c >> 1) & 1);
        const uint32_t smA = sm + st * DN_STAGE;
        const uint32_t smB = smA + 16384;
        #pragma unroll
        for (int j = 0; j < 4; j++) {
            uint32_t a[4][4];
            const uint32_t aBase = smA + (j >> 1) * 8192 +
                (((2 * (j & 1) + aK) << 7) + mw + aRow) * 16;
            #pragma unroll
            for (int i = 0; i < 4; i++) LDSM4(a[i], aBase + i * 256);
            uint32_t b[4][4];
            const uint32_t bBase = smB + (j >> 1) * 8192 +
                (((2 * (j & 1) + bK) << 7) + nw + bRow) * 16;
            #pragma unroll
            for (int nbb = 0; nbb < 4; nbb++) LDSM4(b[nbb], bBase + nbb * 256);
            #pragma unroll
            for (int i = 0; i < 4; i++)
                #pragma unroll
                for (int nbb = 0; nbb < 4; nbb++) {
                    mma_f16(acc[i][2 * nbb + 0], a[i], b[nbb][0], b[nbb][1]);
                    mma_f16(acc[i][2 * nbb + 1], a[i], b[nbb][2], b[nbb][3]);
                }
        }
        __syncthreads();                 // all warps done reading stage st
        if (tid == 0 && c + 2 < 32) issue(c + 2, st);
    }

    // --- epilogue: out = x*(1+w0) + acc + (w1+w2)*b2 --------------------------
    const int g = lane >> 2, tq = lane & 3;
    #pragma unroll
    for (int i = 0; i < 4; i++) {
        const int r0 = m0 + mw + 16 * i + g;
        const float4 wv0 = *(const float4*)&g_wts[4 * r0];
        const float4 wv1 = *(const float4*)&g_wts[4 * (r0 + 8)];
        const float xs0 = 1.f + wv0.x, w120 = wv0.w;
        const float xs1 = 1.f + wv1.x, w121 = wv1.w;
        #pragma unroll
        for (int n = 0; n < 8; n++) {
            const int h = n0 + nw + 8 * n + 2 * tq;
            const float2 xa = *(const float2*)&x[(size_t)r0 * Hd + h];
            const float2 xb = *(const float2*)&x[(size_t)(r0 + 8) * Hd + h];
            const float2 bv = *(const float2*)&b2[h];
            float2 o0, o1;
            o0.x = xa.x * xs0 + acc[i][n][0] + w120 * bv.x;
            o0.y = xa.y * xs0 + acc[i][n][1] + w120 * bv.y;
            o1.x = xb.x * xs1 + acc[i][n][2] + w121 * bv.x;
            o1.y = xb.y * xs1 + acc[i][n][3] + w121 * bv.y;
            *(float2*)&out[(size_t)r0 * Hd + h] = o0;
            *(float2*)&out[(size_t)(r0 + 8) * Hd + h] = o1;
        }
    }
}

// ---------------- launch ------------------------------------------------------
extern "C" void kernel_launch(void* const* d_in, const int* in_sizes, int n_in,
                              void* d_out, int out_size) {
    const float* x   = (const float*)d_in[0];
    const int*   dm  = (const int*)d_in[1];
    const float* gw1 = (const float*)d_in[2];
    const float* gb1 = (const float*)d_in[3];
    const float* gw2 = (const float*)d_in[4];
    const float* gb2 = (const float*)d_in[5];
    const float* sb  = (const float*)d_in[6];
    const float* bb  = (const float*)d_in[7];
    const float* si  = (const float*)d_in[8];
    const float* bi  = (const float*)d_in[9];
    const float* aw1 = (const float*)d_in[10];
    const float* ab1 = (const float*)d_in[11];
    const float* aw2 = (const float*)d_in[12];
    const float* ab2 = (const float*)d_in[13];
    float* out = (float*)d_out;

    cudaFuncSetAttribute(k_up, cudaFuncAttributeMaxDynamicSharedMemorySize, UP_SMEM);
    cudaFuncSetAttribute(k_down, cudaFuncAttributeMaxDynamicSharedMemorySize, DN_SMEM);

    k_prep<<<3200, 256>>>(x, dm, gw1, gb1, gw2, gb2, sb, si, bb, bi, aw1, ab1, aw2);
    k_up<<<dim3(Fd / 64, Td / 128), 128, UP_SMEM>>>();
    k_down<<<dim3(Hd / 128, Td / 128), 128, DN_SMEM>>>(x, ab2, out);
}